// round 6
// baseline (speedup 1.0000x reference)
#include <cuda_runtime.h>

// Problem constants
#define Bb 2
#define Ss 2048
#define Ee 1024
#define Hh 16
#define Dd 64
#define BHh (Bb*Hh)

typedef unsigned long long u64;

// ---- packed fp32x2 helpers (FFMA2: 2x fp32 throughput vs FFMA-3reg) ------
__device__ __forceinline__ u64 ffma2(u64 a, u64 b, u64 c) {
    u64 d; asm("fma.rn.f32x2 %0, %1, %2, %3;" : "=l"(d) : "l"(a), "l"(b), "l"(c));
    return d;
}
__device__ __forceinline__ u64 fmul2(u64 a, u64 b) {
    u64 d; asm("mul.rn.f32x2 %0, %1, %2;" : "=l"(d) : "l"(a), "l"(b));
    return d;
}
__device__ __forceinline__ u64 pack2(float x, float y) {
    u64 r; asm("mov.b64 %0, {%1, %2};" : "=l"(r) : "f"(x), "f"(y));
    return r;
}
__device__ __forceinline__ float2 unpack2(u64 v) {
    float2 r; asm("mov.b64 {%0, %1}, %2;" : "=f"(r.x), "=f"(r.y) : "l"(v));
    return r;
}

// Scratch (device globals -- no allocations allowed)
__device__ float g_q [BHh * Ss * Dd];   // [B*H][S][D]
__device__ float g_k [BHh * Ss * Dd];
__device__ float g_v [BHh * Ss * Dd];
__device__ float g_ao[Bb * Ss * Ee];    // attention output, [B,S,E]

// ---------------------------------------------------------------------------
// SGEMM via FFMA2: C[M,N] = A[M,K] @ W[K,N] + bias
//   MODE 0: scatter columns into Q/K/V [B,H,S,D] layout
//   MODE 1: plain write to Cout
// 128x128 tile, BK=16, 256 threads, 8 rows x 4 col-pairs per thread.
// As2: [k][m] duplicated float2 (broadcast operand pre-packed), stride 130.
// Bs : [k][chunk-permuted 128], so both 16B reads per thread are
//      lane-contiguous (conflict-free).
// ---------------------------------------------------------------------------
#define AS_STR 130
template<int MODE>
__global__ void __launch_bounds__(256)
sgemm_kernel(const float* __restrict__ A, const float* __restrict__ W,
             const float* __restrict__ bias, float* __restrict__ Cout,
             float* __restrict__ Qd, float* __restrict__ Kd, float* __restrict__ Vd,
             int M, int N, int K)
{
    __shared__ float2 As2[16 * AS_STR];   // duplicated pairs
    __shared__ float  Bs [16 * 128];      // chunk-permuted

    const int tid = threadIdx.x;
    const int tx  = tid & 15;        // 16 col groups of 8
    const int ty  = tid >> 4;        // 16 row groups of 8
    const int row0 = blockIdx.y * 128;
    const int col0 = blockIdx.x * 128;

    u64 acc[8][4];
    #pragma unroll
    for (int i = 0; i < 8; i++)
        #pragma unroll
        for (int j = 0; j < 4; j++) acc[i][j] = 0ull;

    // global->smem mapping (2 float4 each for A and B per thread)
    const int f0 = tid, f1 = tid + 256;
    const int ar0 = f0 >> 2, ak0 = (f0 & 3) * 4;
    const int ar1 = f1 >> 2, ak1 = (f1 & 3) * 4;
    const int br0 = f0 >> 5, bc0 = (f0 & 31) * 4;
    const int br1 = f1 >> 5, bc1 = (f1 & 31) * 4;
    // B chunk permutation: col chunk c4 (=bc>>2) -> float offset
    const int c4_0 = bc0 >> 2, c4_1 = bc1 >> 2;
    const int pos0 = ((c4_0 & 1) << 6) + ((c4_0 >> 1) << 2);
    const int pos1 = ((c4_1 & 1) << 6) + ((c4_1 >> 1) << 2);

    float4 pa0, pa1, pb0, pb1;
    pa0 = *(const float4*)(A + (row0 + ar0) * K + ak0);
    pa1 = *(const float4*)(A + (row0 + ar1) * K + ak1);
    pb0 = *(const float4*)(W + br0 * N + col0 + bc0);
    pb1 = *(const float4*)(W + br1 * N + col0 + bc1);

    const int ntiles = K / 16;
    for (int t = 0; t < ntiles; t++) {
        // store prefetched tile to smem (A transposed + duplicated)
        As2[(ak0+0)*AS_STR + ar0] = make_float2(pa0.x, pa0.x);
        As2[(ak0+1)*AS_STR + ar0] = make_float2(pa0.y, pa0.y);
        As2[(ak0+2)*AS_STR + ar0] = make_float2(pa0.z, pa0.z);
        As2[(ak0+3)*AS_STR + ar0] = make_float2(pa0.w, pa0.w);
        As2[(ak1+0)*AS_STR + ar1] = make_float2(pa1.x, pa1.x);
        As2[(ak1+1)*AS_STR + ar1] = make_float2(pa1.y, pa1.y);
        As2[(ak1+2)*AS_STR + ar1] = make_float2(pa1.z, pa1.z);
        As2[(ak1+3)*AS_STR + ar1] = make_float2(pa1.w, pa1.w);
        *(float4*)&Bs[br0*128 + pos0] = pb0;
        *(float4*)&Bs[br1*128 + pos1] = pb1;
        __syncthreads();

        if (t + 1 < ntiles) {
            const float* Ap = A + (t + 1) * 16;
            const float* Wp = W + (size_t)(t + 1) * 16 * N;
            pa0 = *(const float4*)(Ap + (row0 + ar0) * K + ak0);
            pa1 = *(const float4*)(Ap + (row0 + ar1) * K + ak1);
            pb0 = *(const float4*)(Wp + br0 * N + col0 + bc0);
            pb1 = *(const float4*)(Wp + br1 * N + col0 + bc1);
        }

        #pragma unroll
        for (int k = 0; k < 16; k++) {
            ulonglong2 a0 = *(ulonglong2*)&As2[k*AS_STR + ty*8 + 0];
            ulonglong2 a1 = *(ulonglong2*)&As2[k*AS_STR + ty*8 + 2];
            ulonglong2 a2 = *(ulonglong2*)&As2[k*AS_STR + ty*8 + 4];
            ulonglong2 a3 = *(ulonglong2*)&As2[k*AS_STR + ty*8 + 6];
            ulonglong2 b0 = *(ulonglong2*)&Bs[k*128 + tx*4];        // cols tx*8+0..3
            ulonglong2 b1 = *(ulonglong2*)&Bs[k*128 + 64 + tx*4];   // cols tx*8+4..7
            u64 av[8] = {a0.x, a0.y, a1.x, a1.y, a2.x, a2.y, a3.x, a3.y};
            u64 bv[4] = {b0.x, b0.y, b1.x, b1.y};
            #pragma unroll
            for (int i = 0; i < 8; i++)
                #pragma unroll
                for (int j = 0; j < 4; j++)
                    acc[i][j] = ffma2(av[i], bv[j], acc[i][j]);
        }
        __syncthreads();
    }

    // epilogue: acc[i][0..1] -> cols tx*8+0..3 ; acc[i][2..3] -> cols tx*8+4..7
    #pragma unroll
    for (int i = 0; i < 8; i++) {
        int r = row0 + ty*8 + i;
        #pragma unroll
        for (int half = 0; half < 2; half++) {
            int cg = col0 + tx*8 + half*4;
            float2 p0 = unpack2(acc[i][half*2 + 0]);
            float2 p1 = unpack2(acc[i][half*2 + 1]);
            float4 v;
            v.x = p0.x + bias[cg+0];
            v.y = p0.y + bias[cg+1];
            v.z = p1.x + bias[cg+2];
            v.w = p1.y + bias[cg+3];
            if (MODE == 0) {
                int part = cg >> 10;          // 0:q 1:k 2:v  (E=1024)
                int e = cg & 1023;
                int h = e >> 6, d = e & 63;
                int b = r >> 11, s = r & 2047; // S=2048
                float* dst = (part == 0) ? Qd : (part == 1) ? Kd : Vd;
                *(float4*)&dst[(((b*Hh + h)*Ss) + s)*Dd + d] = v;
            } else {
                *(float4*)&Cout[(size_t)r * N + cg] = v;
            }
        }
    }
}

// ---------------------------------------------------------------------------
// fp32 flash attention via FFMA2. Br=Bc=64, D=64, 256 threads, 4x4/thread.
// Qtd: [d][r] duplicated float2 (stride 66); Kt: [d][r] f32 (stride 68);
// Vs: [k][d] f32 (stride 68); Psd: [m][k] duplicated float2 (stride 66).
// scale = 1/(sqrt(64)*2) = 1/16 ; masked entries = -10000 (matches ref).
// ---------------------------------------------------------------------------
#define QS 66
#define KS 68
#define PS 66
#define SM_QTD 0
#define SM_KT  (64*QS*8)                 // 33792
#define SM_VS  (SM_KT + 64*KS*4)        // +17408
#define SM_PSD (SM_VS + 64*KS*4)        // +17408
#define FLASH_SMEM (SM_PSD + 64*PS*8)   // +33792 = 102400

__global__ void __launch_bounds__(256)
flash_kernel(const float* __restrict__ Q, const float* __restrict__ K,
             const float* __restrict__ V, float* __restrict__ O)
{
    extern __shared__ char smraw[];
    float2* Qtd = (float2*)(smraw + SM_QTD);
    float*  Kt  = (float*) (smraw + SM_KT);
    float*  Vs  = (float*) (smraw + SM_VS);
    float2* Psd = (float2*)(smraw + SM_PSD);

    const int tid = threadIdx.x;
    const int tx = tid & 15;         // 4 cols each
    const int ty = tid >> 4;         // 4 rows each
    const int qt = blockIdx.x;       // 0..31
    const int bh = blockIdx.y;       // 0..31
    const int q0 = qt * 64;

    // load Q tile transposed + duplicated (once)
    const float* Qb = Q + ((size_t)bh * Ss + q0) * Dd;
    #pragma unroll
    for (int i = 0; i < 4; i++) {
        int f = tid + i*256;
        int r = f >> 4, d4 = (f & 15) * 4;
        float4 v = *(const float4*)(Qb + r*Dd + d4);
        Qtd[(d4+0)*QS + r] = make_float2(v.x, v.x);
        Qtd[(d4+1)*QS + r] = make_float2(v.y, v.y);
        Qtd[(d4+2)*QS + r] = make_float2(v.z, v.z);
        Qtd[(d4+3)*QS + r] = make_float2(v.w, v.w);
    }

    float m_[4], l_[4];
    u64 o2[4][2];
    #pragma unroll
    for (int i = 0; i < 4; i++) {
        m_[i] = -1e30f; l_[i] = 0.f;
        o2[i][0] = 0ull; o2[i][1] = 0ull;
    }
    __syncthreads();

    for (int kt = 0; kt <= qt; kt++) {
        const int k0 = kt * 64;
        const float* Kb = K + ((size_t)bh * Ss + k0) * Dd;
        const float* Vb = V + ((size_t)bh * Ss + k0) * Dd;
        #pragma unroll
        for (int i = 0; i < 4; i++) {
            int f = tid + i*256;
            int r = f >> 4, d4 = (f & 15) * 4;
            float4 kv = *(const float4*)(Kb + r*Dd + d4);
            Kt[(d4+0)*KS + r] = kv.x;
            Kt[(d4+1)*KS + r] = kv.y;
            Kt[(d4+2)*KS + r] = kv.z;
            Kt[(d4+3)*KS + r] = kv.w;
            float4 vv = *(const float4*)(Vb + r*Dd + d4);
            *(float4*)&Vs[r*KS + d4] = vv;
        }
        __syncthreads();

        // S = Q K^T  (4 rows x 2 col-pairs packed per thread)
        u64 s2[4][2];
        #pragma unroll
        for (int i = 0; i < 4; i++) { s2[i][0] = 0ull; s2[i][1] = 0ull; }

        #pragma unroll 16
        for (int d = 0; d < 64; d++) {
            ulonglong2 q0p = *(ulonglong2*)&Qtd[d*QS + ty*4 + 0];
            ulonglong2 q1p = *(ulonglong2*)&Qtd[d*QS + ty*4 + 2];
            ulonglong2 kv  = *(ulonglong2*)&Kt [d*KS + tx*4];
            u64 qd[4] = {q0p.x, q0p.y, q1p.x, q1p.y};
            #pragma unroll
            for (int i = 0; i < 4; i++) {
                s2[i][0] = ffma2(qd[i], kv.x, s2[i][0]);
                s2[i][1] = ffma2(qd[i], kv.y, s2[i][1]);
            }
        }

        // unpack, scale, mask
        float s[4][4];
        const float sc = 1.0f / 16.0f;   // 1/(sqrt(64)*layer_idx)
        const bool diag = (kt == qt);
        #pragma unroll
        for (int i = 0; i < 4; i++) {
            float2 u0 = unpack2(s2[i][0]);
            float2 u1 = unpack2(s2[i][1]);
            s[i][0] = u0.x * sc; s[i][1] = u0.y * sc;
            s[i][2] = u1.x * sc; s[i][3] = u1.y * sc;
            if (diag) {
                #pragma unroll
                for (int j = 0; j < 4; j++)
                    if (k0 + tx*4 + j > q0 + ty*4 + i) s[i][j] = -10000.0f;
            }
        }

        // online softmax (rows shared by 16 tx-threads; shfl within 16-group)
        #pragma unroll
        for (int i = 0; i < 4; i++) {
            float rm = fmaxf(fmaxf(s[i][0], s[i][1]), fmaxf(s[i][2], s[i][3]));
            #pragma unroll
            for (int off = 8; off > 0; off >>= 1)
                rm = fmaxf(rm, __shfl_xor_sync(0xffffffffu, rm, off));
            float mn = fmaxf(m_[i], rm);
            float c = __expf(m_[i] - mn);
            m_[i] = mn;
            float rs = 0.f;
            #pragma unroll
            for (int j = 0; j < 4; j++) {
                s[i][j] = __expf(s[i][j] - mn);
                rs += s[i][j];
            }
            #pragma unroll
            for (int off = 8; off > 0; off >>= 1)
                rs += __shfl_xor_sync(0xffffffffu, rs, off);
            l_[i] = l_[i] * c + rs;
            u64 cc = pack2(c, c);
            o2[i][0] = fmul2(o2[i][0], cc);
            o2[i][1] = fmul2(o2[i][1], cc);
        }

        // store P duplicated
        #pragma unroll
        for (int i = 0; i < 4; i++)
            #pragma unroll
            for (int j = 0; j < 4; j++)
                Psd[(ty*4+i)*PS + tx*4 + j] = make_float2(s[i][j], s[i][j]);
        __syncthreads();

        // O += P @ V  (packed over the d/output dim)
        #pragma unroll 16
        for (int k = 0; k < 64; k++) {
            ulonglong2 vv = *(ulonglong2*)&Vs[k*KS + tx*4];
            #pragma unroll
            for (int i = 0; i < 4; i++) {
                u64 pd = *(u64*)&Psd[(ty*4+i)*PS + k];
                o2[i][0] = ffma2(pd, vv.x, o2[i][0]);
                o2[i][1] = ffma2(pd, vv.y, o2[i][1]);
            }
        }
        __syncthreads();
    }

    // finalize + write merged-head layout [B,S,E]
    const int b = bh >> 4, h = bh & 15;
    #pragma unroll
    for (int i = 0; i < 4; i++) {
        float inv = 1.0f / l_[i];
        int srow = q0 + ty*4 + i;
        float2 oa = unpack2(o2[i][0]);
        float2 ob = unpack2(o2[i][1]);
        float4 v = make_float4(oa.x*inv, oa.y*inv, ob.x*inv, ob.y*inv);
        *(float4*)&O[((size_t)(b*Ss + srow)) * Ee + h*64 + tx*4] = v;
    }
}

// ---------------------------------------------------------------------------
extern "C" void kernel_launch(void* const* d_in, const int* in_sizes, int n_in,
                              void* d_out, int out_size)
{
    const float* hs     = (const float*)d_in[0];  // [B,S,E]
    const float* w_attn = (const float*)d_in[1];  // [E,3E]
    const float* b_attn = (const float*)d_in[2];  // [3E]
    const float* w_proj = (const float*)d_in[3];  // [E,E]
    const float* b_proj = (const float*)d_in[4];  // [E]
    float* out = (float*)d_out;                   // [B,S,E]

    float *qp, *kp, *vp, *aop;
    cudaGetSymbolAddress((void**)&qp,  g_q);
    cudaGetSymbolAddress((void**)&kp,  g_k);
    cudaGetSymbolAddress((void**)&vp,  g_v);
    cudaGetSymbolAddress((void**)&aop, g_ao);

    // 1) QKV GEMM + scatter into [B,H,S,D]
    sgemm_kernel<0><<<dim3(3*Ee/128, (Bb*Ss)/128), 256>>>(
        hs, w_attn, b_attn, nullptr, qp, kp, vp, Bb*Ss, 3*Ee, Ee);

    // 2) causal flash attention
    cudaFuncSetAttribute(flash_kernel,
                         cudaFuncAttributeMaxDynamicSharedMemorySize, FLASH_SMEM);
    flash_kernel<<<dim3(Ss/64, BHh), 256, FLASH_SMEM>>>(qp, kp, vp, aop);

    // 3) output projection -> d_out
    sgemm_kernel<1><<<dim3(Ee/128, (Bb*Ss)/128), 256>>>(
        aop, w_proj, b_proj, out, nullptr, nullptr, nullptr, Bb*Ss, Ee, Ee);
}

// round 14
// speedup vs baseline: 1.7452x; 1.7452x over previous
#include <cuda_runtime.h>
#include <cuda_bf16.h>
#include <cstdint>

// Problem constants
#define Bb 2
#define Ss 2048
#define Ee 1024
#define Hh 16
#define Dd 64
#define BHh (Bb*Hh)

typedef unsigned int u32;

// ---------------- device scratch (no allocations allowed) ----------------
// Fragment-packed operands for mma.sync.m16n8k16:
//  A-pack: uint4 index ((mt*64 + ks)*32 + lane) ; regs a0..a3 in uint4
//  B-pack: uint2 index ((nt*64 + ks)*32 + lane) ; regs b0..b1 in uint2
__device__ uint4 g_pxh[256*64*32], g_pxl[256*64*32];   // hidden  [mt=256]
__device__ uint4 g_pah[256*64*32], g_pal[256*64*32];   // attn-out packed
__device__ uint4 g_pwah[384*64*16], g_pwal[384*64*16]; // W_attn^T packed [nt=384]
__device__ uint4 g_pwph[128*64*16], g_pwpl[128*64*16]; // W_proj^T packed [nt=128]
__device__ float g_q[BHh*Ss*Dd], g_k[BHh*Ss*Dd], g_v[BHh*Ss*Dd];
__device__ float g_ao[Bb*Ss*Ee];

__device__ __forceinline__ u32 bfpack(float a, float b) {
    __nv_bfloat16 ha = __float2bfloat16(a), hb = __float2bfloat16(b);
    return (u32)__bfloat16_as_ushort(ha) | ((u32)__bfloat16_as_ushort(hb) << 16);
}
__device__ __forceinline__ float bflow(float x) {
    return x - __bfloat162float(__float2bfloat16(x));
}

// ---------------- mma.sync wrapper (bf16 -> fp32) ----------------
__device__ __forceinline__ void mma_bf16(float4& c, uint4 a, uint2 b) {
    asm volatile("mma.sync.aligned.m16n8k16.row.col.f32.bf16.bf16.f32 "
        "{%0,%1,%2,%3}, {%4,%5,%6,%7}, {%8,%9}, {%0,%1,%2,%3};"
        : "+f"(c.x), "+f"(c.y), "+f"(c.z), "+f"(c.w)
        : "r"(a.x), "r"(a.y), "r"(a.z), "r"(a.w), "r"(b.x), "r"(b.y));
}

// ---------------- pre-pass: split fp32 activations -> packed bf16 hi/lo ----
// X [4096][1024] row-major. Element (m,k): mt=m>>4, ks=k>>4,
// lane=(m&7)*4+((k&7)>>1), reg=((k>>3)&1)*2+((m>>3)&1), half=k&1.
// u32 index = 4*((mt*64+ks)*32 + lane) + reg ; lane advances by 1 per k-pair
// => +4 u32 per pair (THE R12 BUG: was +16).
__global__ void __launch_bounds__(256)
split_pack_A(const float* __restrict__ X, uint4* __restrict__ H4, uint4* __restrict__ L4)
{
    u32* H = (u32*)H4; u32* L = (u32*)L4;
    int gid = blockIdx.x * 256 + threadIdx.x;   // one per 8 elems
    int m = gid >> 7;
    int kg = (gid & 127) * 8;
    const float* p = X + (size_t)m * 1024 + kg;
    float4 v0 = *(const float4*)p, v1 = *(const float4*)(p + 4);
    float xs[8] = {v0.x, v0.y, v0.z, v0.w, v1.x, v1.y, v1.z, v1.w};
    int mt = m >> 4, ks = kg >> 4, mhi = (m >> 3) & 1, k8 = (kg >> 3) & 1;
    int base = (((mt*64 + ks)*32) + (m & 7)*4) * 4 + (k8*2 + mhi);
    #pragma unroll
    for (int t = 0; t < 4; t++) {
        float e0 = xs[2*t], e1 = xs[2*t+1];
        H[base + t*4] = bfpack(e0, e1);
        L[base + t*4] = bfpack(bflow(e0), bflow(e1));
    }
}

// ---------------- pre-pass: transpose+split weights -> packed bf16 hi/lo ---
// W [1024 rows=K][N cols] fp32 -> B-pack over [N][K].
// u32 index = 2*((nt*64+ks)*32 + lane) + k8 ; lane = (n&7)*4 + ((k&7)>>1).
__global__ void __launch_bounds__(256)
tsplit_pack_B(const float* __restrict__ W, uint4* __restrict__ H4, uint4* __restrict__ L4, int N)
{
    u32* H = (u32*)H4; u32* L = (u32*)L4;
    __shared__ float t[32][33];
    const int k0 = blockIdx.y * 32, n0 = blockIdx.x * 32;
    const int r = threadIdx.x >> 3, c4 = (threadIdx.x & 7) * 4;
    float4 v = *(const float4*)&W[(size_t)(k0 + r) * N + n0 + c4];
    t[r][c4+0] = v.x; t[r][c4+1] = v.y; t[r][c4+2] = v.z; t[r][c4+3] = v.w;
    __syncthreads();
    // this thread outputs element run: n = n0+r, k = k0+c4 .. +3
    const int n = n0 + r, kk = k0 + c4;
    float e[4];
    #pragma unroll
    for (int i = 0; i < 4; i++) e[i] = t[c4 + i][r];
    int nt = n >> 3, ks = kk >> 4, k8 = (kk >> 3) & 1;
    int tp = (kk & 7) >> 1;                       // first k-pair slot
    int idx = (((nt*64 + ks)*32) + (n & 7)*4 + tp) * 2 + k8;
    H[idx]     = bfpack(e[0], e[1]);
    H[idx + 2] = bfpack(e[2], e[3]);
    L[idx]     = bfpack(bflow(e[0]), bflow(e[1]));
    L[idx + 2] = bfpack(bflow(e[2]), bflow(e[3]));
}

// ---------------- tensor-core (mma.sync) bf16-split GEMM ----------------
// C[M=4096, N] = A @ B^T + bias (fp32-equiv via hi*hi + hi*lo + lo*hi).
// MODE 0: scatter into Q/K/V [B,H,S,D] (N=3072); MODE 1: plain write (N=Ndim).
// CTA 128x128, BK=32, 8 warps (2 M x 4 N), warp tile 64x32.
template<int MODE>
__global__ void __launch_bounds__(256)
gemm_mma(const uint4* __restrict__ Ah, const uint4* __restrict__ Al,
         const uint4* __restrict__ Bh, const uint4* __restrict__ Bl,
         const float* __restrict__ bias, float* __restrict__ Cout,
         float* __restrict__ Qd, float* __restrict__ Kd, float* __restrict__ Vd,
         int Ndim)
{
    __shared__ uint4 sAh[512], sAl[512], sBh[512], sBl[512];  // 8KB each

    const int tid = threadIdx.x;
    const int lane = tid & 31, wid = tid >> 5;
    const int wm = wid & 1, wn = wid >> 1;
    const int m0 = blockIdx.y * 128, n0 = blockIdx.x * 128;
    const int m0t = m0 >> 4, n0t = n0 >> 3;      // tile bases

    // writer index decomposition (2 uint4 per matrix per thread per chunk)
    const int ia0 = tid, ia1 = tid + 256;
    #define A_G(idx) ((((size_t)(m0t + ((idx) >> 6)) * 64 + (((idx) >> 5) & 1)) * 32) + ((idx) & 31))
    #define A_S(idx) (((((idx) >> 5) & 1) * 8 + ((idx) >> 6)) * 32 + ((idx) & 31))
    #define B_G(idx) ((((size_t)(n0t + ((idx) >> 5)) * 64 + (((idx) >> 4) & 1)) * 16) + ((idx) & 15))
    #define B_S(idx) (((((idx) >> 4) & 1) * 16 + ((idx) >> 5)) * 16 + ((idx) & 15))
    const size_t ag0 = A_G(ia0), ag1 = A_G(ia1);
    const size_t bg0 = B_G(ia0), bg1 = B_G(ia1);
    const int as0 = A_S(ia0), as1 = A_S(ia1);
    const int bs0 = B_S(ia0), bs1 = B_S(ia1);

    float4 acc[4][4];
    #pragma unroll
    for (int i = 0; i < 4; i++)
        #pragma unroll
        for (int j = 0; j < 4; j++) acc[i][j] = make_float4(0.f, 0.f, 0.f, 0.f);

    uint4 rAh0, rAh1, rAl0, rAl1, rBh0, rBh1, rBl0, rBl1;
    #define LOADC(CK) do { \
        size_t ao = (size_t)(CK) * 64, bo = (size_t)(CK) * 32; \
        rAh0 = Ah[ag0 + ao]; rAh1 = Ah[ag1 + ao]; \
        rAl0 = Al[ag0 + ao]; rAl1 = Al[ag1 + ao]; \
        rBh0 = Bh[bg0 + bo]; rBh1 = Bh[bg1 + bo]; \
        rBl0 = Bl[bg0 + bo]; rBl1 = Bl[bg1 + bo]; \
    } while (0)

    LOADC(0);
    const uint2* sBh2 = (const uint2*)sBh;
    const uint2* sBl2 = (const uint2*)sBl;

    for (int ck = 0; ck < 32; ck++) {
        if (ck) __syncthreads();                 // prior chunk reads done
        sAh[as0] = rAh0; sAh[as1] = rAh1;
        sAl[as0] = rAl0; sAl[as1] = rAl1;
        sBh[bs0] = rBh0; sBh[bs1] = rBh1;
        sBl[bs0] = rBl0; sBl[bs1] = rBl1;
        __syncthreads();
        if (ck + 1 < 32) LOADC(ck + 1);          // overlap with mma

        #pragma unroll
        for (int ks = 0; ks < 2; ks++) {
            uint2 bh[4], bl[4];
            #pragma unroll
            for (int j = 0; j < 4; j++) {
                int bi = (ks*16 + wn*4 + j)*32 + lane;
                bh[j] = sBh2[bi];
                bl[j] = sBl2[bi];
            }
            #pragma unroll
            for (int i = 0; i < 4; i++) {
                int aidx = (ks*8 + wm*4 + i)*32 + lane;
                uint4 ah = sAh[aidx];
                uint4 al = sAl[aidx];
                #pragma unroll
                for (int j = 0; j < 4; j++) {
                    mma_bf16(acc[i][j], ah, bh[j]);
                    mma_bf16(acc[i][j], ah, bl[j]);
                    mma_bf16(acc[i][j], al, bh[j]);
                }
            }
        }
    }

    // epilogue: c0,c1 -> (g, 2t..2t+1); c2,c3 -> (g+8, ...)
    const int g = lane >> 2, t2 = (lane & 3) * 2;
    #pragma unroll
    for (int i = 0; i < 4; i++) {
        int r1 = m0 + wm*64 + i*16 + g;
        #pragma unroll
        for (int j = 0; j < 4; j++) {
            int cg = n0 + wn*32 + j*8 + t2;
            float2 bs = *(const float2*)(bias + cg);
            float2 vlo = make_float2(acc[i][j].x + bs.x, acc[i][j].y + bs.y);
            float2 vhi = make_float2(acc[i][j].z + bs.x, acc[i][j].w + bs.y);
            if (MODE == 0) {
                int part = cg >> 10;             // 0:q 1:k 2:v
                int e = cg & 1023;
                int h = e >> 6, d = e & 63;
                float* dst = (part == 0) ? Qd : (part == 1) ? Kd : Vd;
                int b1 = r1 >> 11, s1 = r1 & 2047;
                *(float2*)&dst[(((b1*Hh + h)*Ss) + s1)*Dd + d] = vlo;
                int r2 = r1 + 8;
                int b2 = r2 >> 11, s2 = r2 & 2047;
                *(float2*)&dst[(((b2*Hh + h)*Ss) + s2)*Dd + d] = vhi;
            } else {
                *(float2*)&Cout[(size_t)r1 * Ndim + cg] = vlo;
                *(float2*)&Cout[(size_t)(r1 + 8) * Ndim + cg] = vhi;
            }
        }
    }
}

// ---------------------------------------------------------------------------
// fp32 flash attention (R3 version, verified). Br=Bc=64, 256 thr, 4x4/thread.
// ---------------------------------------------------------------------------
__global__ void __launch_bounds__(256)
flash_kernel(const float* __restrict__ Q, const float* __restrict__ K,
             const float* __restrict__ V, float* __restrict__ O)
{
    extern __shared__ float sm[];
    float* Qt = sm;                  // [64][68] d-major
    float* Kt = sm + 64*68;
    float* Vs = sm + 2*64*68;
    float* Ps = sm + 3*64*68;

    const int tid = threadIdx.x;
    const int tx = tid & 15;
    const int ty = tid >> 4;
    const int qt = blockIdx.x;
    const int bh = blockIdx.y;
    const int q0 = qt * 64;

    const float* Qb = Q + ((size_t)bh * Ss + q0) * Dd;
    #pragma unroll
    for (int i = 0; i < 4; i++) {
        int f = tid + i*256;
        int r = f >> 4, d4 = (f & 15) * 4;
        float4 v = *(const float4*)(Qb + r*Dd + d4);
        Qt[(d4+0)*68 + r] = v.x;
        Qt[(d4+1)*68 + r] = v.y;
        Qt[(d4+2)*68 + r] = v.z;
        Qt[(d4+3)*68 + r] = v.w;
    }

    float m_[4], l_[4], o[4][4];
    #pragma unroll
    for (int i = 0; i < 4; i++) {
        m_[i] = -1e30f; l_[i] = 0.f;
        #pragma unroll
        for (int j = 0; j < 4; j++) o[i][j] = 0.f;
    }
    __syncthreads();

    for (int kt = 0; kt <= qt; kt++) {
        const int k0 = kt * 64;
        const float* Kb = K + ((size_t)bh * Ss + k0) * Dd;
        const float* Vb = V + ((size_t)bh * Ss + k0) * Dd;
        #pragma unroll
        for (int i = 0; i < 4; i++) {
            int f = tid + i*256;
            int r = f >> 4, d4 = (f & 15) * 4;
            float4 kv = *(const float4*)(Kb + r*Dd + d4);
            Kt[(d4+0)*68 + r] = kv.x;
            Kt[(d4+1)*68 + r] = kv.y;
            Kt[(d4+2)*68 + r] = kv.z;
            Kt[(d4+3)*68 + r] = kv.w;
            float4 vv = *(const float4*)(Vb + r*Dd + d4);
            *(float4*)&Vs[r*68 + d4] = vv;
        }
        __syncthreads();

        float s[4][4];
        #pragma unroll
        for (int i = 0; i < 4; i++)
            #pragma unroll
            for (int j = 0; j < 4; j++) s[i][j] = 0.f;

        #pragma unroll 16
        for (int d = 0; d < 64; d++) {
            float4 qv = *(float4*)&Qt[d*68 + ty*4];
            float4 kv = *(float4*)&Kt[d*68 + tx*4];
            float qa[4] = {qv.x, qv.y, qv.z, qv.w};
            float ka[4] = {kv.x, kv.y, kv.z, kv.w};
            #pragma unroll
            for (int i = 0; i < 4; i++)
                #pragma unroll
                for (int j = 0; j < 4; j++)
                    s[i][j] = fmaf(qa[i], ka[j], s[i][j]);
        }

        const float sc = 1.0f / 16.0f;
        const bool diag = (kt == qt);
        #pragma unroll
        for (int i = 0; i < 4; i++)
            #pragma unroll
            for (int j = 0; j < 4; j++) {
                s[i][j] *= sc;
                if (diag && (k0 + tx*4 + j > q0 + ty*4 + i)) s[i][j] = -10000.0f;
            }

        #pragma unroll
        for (int i = 0; i < 4; i++) {
            float rm = fmaxf(fmaxf(s[i][0], s[i][1]), fmaxf(s[i][2], s[i][3]));
            #pragma unroll
            for (int off = 8; off > 0; off >>= 1)
                rm = fmaxf(rm, __shfl_xor_sync(0xffffffffu, rm, off));
            float mn = fmaxf(m_[i], rm);
            float c = __expf(m_[i] - mn);
            m_[i] = mn;
            float rs = 0.f;
            #pragma unroll
            for (int j = 0; j < 4; j++) {
                s[i][j] = __expf(s[i][j] - mn);
                rs += s[i][j];
            }
            #pragma unroll
            for (int off = 8; off > 0; off >>= 1)
                rs += __shfl_xor_sync(0xffffffffu, rs, off);
            l_[i] = l_[i] * c + rs;
            #pragma unroll
            for (int j = 0; j < 4; j++) o[i][j] *= c;
        }

        #pragma unroll
        for (int i = 0; i < 4; i++)
            *(float4*)&Ps[(ty*4+i)*68 + tx*4] =
                make_float4(s[i][0], s[i][1], s[i][2], s[i][3]);
        __syncthreads();

        #pragma unroll 16
        for (int k = 0; k < 64; k++) {
            float4 vv = *(float4*)&Vs[k*68 + tx*4];
            #pragma unroll
            for (int i = 0; i < 4; i++) {
                float p = Ps[(ty*4+i)*68 + k];
                o[i][0] = fmaf(p, vv.x, o[i][0]);
                o[i][1] = fmaf(p, vv.y, o[i][1]);
                o[i][2] = fmaf(p, vv.z, o[i][2]);
                o[i][3] = fmaf(p, vv.w, o[i][3]);
            }
        }
        __syncthreads();
    }

    const int b = bh >> 4, h = bh & 15;
    #pragma unroll
    for (int i = 0; i < 4; i++) {
        float inv = 1.0f / l_[i];
        int srow = q0 + ty*4 + i;
        float4 v = make_float4(o[i][0]*inv, o[i][1]*inv, o[i][2]*inv, o[i][3]*inv);
        *(float4*)&O[((size_t)(b*Ss + srow)) * Ee + h*64 + tx*4] = v;
    }
}

// ---------------------------------------------------------------------------
extern "C" void kernel_launch(void* const* d_in, const int* in_sizes, int n_in,
                              void* d_out, int out_size)
{
    const float* hs     = (const float*)d_in[0];
    const float* w_attn = (const float*)d_in[1];
    const float* b_attn = (const float*)d_in[2];
    const float* w_proj = (const float*)d_in[3];
    const float* b_proj = (const float*)d_in[4];
    float* out = (float*)d_out;

    uint4 *pxh, *pxl, *pah, *pal, *pwah, *pwal, *pwph, *pwpl;
    float *qp, *kp, *vp, *aop;
    cudaGetSymbolAddress((void**)&pxh,  g_pxh);  cudaGetSymbolAddress((void**)&pxl,  g_pxl);
    cudaGetSymbolAddress((void**)&pah,  g_pah);  cudaGetSymbolAddress((void**)&pal,  g_pal);
    cudaGetSymbolAddress((void**)&pwah, g_pwah); cudaGetSymbolAddress((void**)&pwal, g_pwal);
    cudaGetSymbolAddress((void**)&pwph, g_pwph); cudaGetSymbolAddress((void**)&pwpl, g_pwpl);
    cudaGetSymbolAddress((void**)&qp,   g_q);    cudaGetSymbolAddress((void**)&kp,   g_k);
    cudaGetSymbolAddress((void**)&vp,   g_v);    cudaGetSymbolAddress((void**)&aop,  g_ao);

    const int flash_smem = 4 * 64 * 68 * (int)sizeof(float);  // 69632 B
    cudaFuncSetAttribute(flash_kernel,
                         cudaFuncAttributeMaxDynamicSharedMemorySize, flash_smem);

    // 0) pack inputs (split + fragment layout)
    split_pack_A<<<(Bb*Ss*Ee)/(256*8), 256>>>(hs, pxh, pxl);
    tsplit_pack_B<<<dim3(3*Ee/32, Ee/32), 256>>>(w_attn, pwah, pwal, 3*Ee);
    tsplit_pack_B<<<dim3(Ee/32,   Ee/32), 256>>>(w_proj, pwph, pwpl, Ee);

    // 1) QKV GEMM (tensor cores) + scatter into [B,H,S,D]
    gemm_mma<0><<<dim3(3*Ee/128, (Bb*Ss)/128), 256>>>(
        pxh, pxl, pwah, pwal, b_attn, nullptr, qp, kp, vp, 3*Ee);

    // 2) causal flash attention (fp32)
    flash_kernel<<<dim3(Ss/64, BHh), 256, flash_smem>>>(qp, kp, vp, aop);

    // 3) pack attn output, projection GEMM (tensor cores) -> d_out
    split_pack_A<<<(Bb*Ss*Ee)/(256*8), 256>>>(aop, pah, pal);
    gemm_mma<1><<<dim3(Ee/128, (Bb*Ss)/128), 256>>>(
        pah, pal, pwph, pwpl, b_proj, out, nullptr, nullptr, nullptr, Ee);
}

// round 15
// speedup vs baseline: 2.9575x; 1.6947x over previous
#include <cuda_runtime.h>
#include <cuda_bf16.h>
#include <cstdint>

// Problem constants
#define Bb 2
#define Ss 2048
#define Ee 1024
#define Hh 16
#define Dd 64
#define BHh (Bb*Hh)

typedef unsigned int u32;
typedef unsigned short u16;

// ---------------- device scratch (no allocations allowed) ----------------
// GEMM operand packs (verified R14 layout):
//  A-pack u32 idx = ((mt*NKS + ks)*32 + lane)*4 + reg ; lane=(m&7)*4+((k&7)>>1),
//  reg=((k>>3)&1)*2+((m>>3)&1)
//  B-pack u32 idx = ((nt*NKS + ks)*32 + lane)*2 + k8  ; lane=(n&7)*4+((k&7)>>1)
__device__ uint4 g_pxh[256*64*32], g_pxl[256*64*32];   // hidden A-pack [mt=256][ks=64]
__device__ uint4 g_pah[256*64*32], g_pal[256*64*32];   // attn-out A-pack (proj input)
__device__ uint4 g_pwah[384*64*16], g_pwal[384*64*16]; // W_attn^T B-pack
__device__ uint4 g_pwph[128*64*16], g_pwpl[128*64*16]; // W_proj^T B-pack
// Flash packs (per bh):
//  Q A-pack:  u32 idx = (((bh*128+mt)*4+ks)*32+lane)*4+reg   (m=s, k=d)
//  K B-pack:  u32 idx = ((((bh*32+kt)*8+nt)*4+ks)*32+lane)*2+k8  (n=key, k=d)
//  V B-pack:  same shape, (n=d, k=key)
__device__ u32 g_qph[32*128*4*32*4], g_qpl[32*128*4*32*4];
__device__ u32 g_kph[32*32*8*4*32*2], g_kpl[32*32*8*4*32*2];
__device__ u32 g_vph[32*32*8*4*32*2], g_vpl[32*32*8*4*32*2];

__device__ __forceinline__ u32 bfpack(float a, float b) {
    __nv_bfloat16 ha = __float2bfloat16(a), hb = __float2bfloat16(b);
    return (u32)__bfloat16_as_ushort(ha) | ((u32)__bfloat16_as_ushort(hb) << 16);
}
__device__ __forceinline__ float bflow(float x) {
    return x - __bfloat162float(__float2bfloat16(x));
}
__device__ __forceinline__ u16 bfbits(float x) {
    return __bfloat16_as_ushort(__float2bfloat16(x));
}

// ---------------- mma.sync wrapper (bf16 -> fp32) ----------------
__device__ __forceinline__ void mma_bf16(float4& c, uint4 a, uint2 b) {
    asm volatile("mma.sync.aligned.m16n8k16.row.col.f32.bf16.bf16.f32 "
        "{%0,%1,%2,%3}, {%4,%5,%6,%7}, {%8,%9}, {%0,%1,%2,%3};"
        : "+f"(c.x), "+f"(c.y), "+f"(c.z), "+f"(c.w)
        : "r"(a.x), "r"(a.y), "r"(a.z), "r"(a.w), "r"(b.x), "r"(b.y));
}

// ---------------- pre-pass: split fp32 activations -> packed bf16 hi/lo ----
__global__ void __launch_bounds__(256)
split_pack_A(const float* __restrict__ X, uint4* __restrict__ H4, uint4* __restrict__ L4)
{
    u32* H = (u32*)H4; u32* L = (u32*)L4;
    int gid = blockIdx.x * 256 + threadIdx.x;   // one per 8 elems
    int m = gid >> 7;
    int kg = (gid & 127) * 8;
    const float* p = X + (size_t)m * 1024 + kg;
    float4 v0 = *(const float4*)p, v1 = *(const float4*)(p + 4);
    float xs[8] = {v0.x, v0.y, v0.z, v0.w, v1.x, v1.y, v1.z, v1.w};
    int mt = m >> 4, ks = kg >> 4, mhi = (m >> 3) & 1, k8 = (kg >> 3) & 1;
    int base = (((mt*64 + ks)*32) + (m & 7)*4) * 4 + (k8*2 + mhi);
    #pragma unroll
    for (int t = 0; t < 4; t++) {
        float e0 = xs[2*t], e1 = xs[2*t+1];
        H[base + t*4] = bfpack(e0, e1);
        L[base + t*4] = bfpack(bflow(e0), bflow(e1));
    }
}

// ---------------- pre-pass: transpose+split weights -> packed bf16 hi/lo ---
__global__ void __launch_bounds__(256)
tsplit_pack_B(const float* __restrict__ W, uint4* __restrict__ H4, uint4* __restrict__ L4, int N)
{
    u32* H = (u32*)H4; u32* L = (u32*)L4;
    __shared__ float t[32][33];
    const int k0 = blockIdx.y * 32, n0 = blockIdx.x * 32;
    const int r = threadIdx.x >> 3, c4 = (threadIdx.x & 7) * 4;
    float4 v = *(const float4*)&W[(size_t)(k0 + r) * N + n0 + c4];
    t[r][c4+0] = v.x; t[r][c4+1] = v.y; t[r][c4+2] = v.z; t[r][c4+3] = v.w;
    __syncthreads();
    const int n = n0 + r, kk = k0 + c4;
    float e[4];
    #pragma unroll
    for (int i = 0; i < 4; i++) e[i] = t[c4 + i][r];
    int nt = n >> 3, ks = kk >> 4, k8 = (kk >> 3) & 1;
    int tp = (kk & 7) >> 1;
    int idx = (((nt*64 + ks)*32) + (n & 7)*4 + tp) * 2 + k8;
    H[idx]     = bfpack(e[0], e[1]);
    H[idx + 2] = bfpack(e[2], e[3]);
    L[idx]     = bfpack(bflow(e[0]), bflow(e[1]));
    L[idx + 2] = bfpack(bflow(e[2]), bflow(e[3]));
}

// ---------------- tensor-core (mma.sync) bf16-split GEMM ----------------
// MODE 0: epilogue packs Q (prescaled 1/16) / K / V into flash fragment packs.
// MODE 1: plain fp32 write to Cout.
template<int MODE>
__global__ void __launch_bounds__(256)
gemm_mma(const uint4* __restrict__ Ah, const uint4* __restrict__ Al,
         const uint4* __restrict__ Bh, const uint4* __restrict__ Bl,
         const float* __restrict__ bias, float* __restrict__ Cout,
         u32* __restrict__ QH, u32* __restrict__ QL,
         u32* __restrict__ KH, u32* __restrict__ KL,
         u16* __restrict__ VHs, u16* __restrict__ VLs,
         int Ndim)
{
    __shared__ uint4 sAh[512], sAl[512], sBh[512], sBl[512];

    const int tid = threadIdx.x;
    const int lane = tid & 31, wid = tid >> 5;
    const int wm = wid & 1, wn = wid >> 1;
    const int m0 = blockIdx.y * 128, n0 = blockIdx.x * 128;
    const int m0t = m0 >> 4, n0t = n0 >> 3;

    const int ia0 = tid, ia1 = tid + 256;
    #define A_G(idx) ((((size_t)(m0t + ((idx) >> 6)) * 64 + (((idx) >> 5) & 1)) * 32) + ((idx) & 31))
    #define A_S(idx) (((((idx) >> 5) & 1) * 8 + ((idx) >> 6)) * 32 + ((idx) & 31))
    #define B_G(idx) ((((size_t)(n0t + ((idx) >> 5)) * 64 + (((idx) >> 4) & 1)) * 16) + ((idx) & 15))
    #define B_S(idx) (((((idx) >> 4) & 1) * 16 + ((idx) >> 5)) * 16 + ((idx) & 15))
    const size_t ag0 = A_G(ia0), ag1 = A_G(ia1);
    const size_t bg0 = B_G(ia0), bg1 = B_G(ia1);
    const int as0 = A_S(ia0), as1 = A_S(ia1);
    const int bs0 = B_S(ia0), bs1 = B_S(ia1);

    float4 acc[4][4];
    #pragma unroll
    for (int i = 0; i < 4; i++)
        #pragma unroll
        for (int j = 0; j < 4; j++) acc[i][j] = make_float4(0.f, 0.f, 0.f, 0.f);

    uint4 rAh0, rAh1, rAl0, rAl1, rBh0, rBh1, rBl0, rBl1;
    #define LOADC(CK) do { \
        size_t ao = (size_t)(CK) * 64, bo = (size_t)(CK) * 32; \
        rAh0 = Ah[ag0 + ao]; rAh1 = Ah[ag1 + ao]; \
        rAl0 = Al[ag0 + ao]; rAl1 = Al[ag1 + ao]; \
        rBh0 = Bh[bg0 + bo]; rBh1 = Bh[bg1 + bo]; \
        rBl0 = Bl[bg0 + bo]; rBl1 = Bl[bg1 + bo]; \
    } while (0)

    LOADC(0);
    const uint2* sBh2 = (const uint2*)sBh;
    const uint2* sBl2 = (const uint2*)sBl;

    for (int ck = 0; ck < 32; ck++) {
        if (ck) __syncthreads();
        sAh[as0] = rAh0; sAh[as1] = rAh1;
        sAl[as0] = rAl0; sAl[as1] = rAl1;
        sBh[bs0] = rBh0; sBh[bs1] = rBh1;
        sBl[bs0] = rBl0; sBl[bs1] = rBl1;
        __syncthreads();
        if (ck + 1 < 32) LOADC(ck + 1);

        #pragma unroll
        for (int ks = 0; ks < 2; ks++) {
            uint2 bh[4], bl[4];
            #pragma unroll
            for (int j = 0; j < 4; j++) {
                int bi = (ks*16 + wn*4 + j)*32 + lane;
                bh[j] = sBh2[bi];
                bl[j] = sBl2[bi];
            }
            #pragma unroll
            for (int i = 0; i < 4; i++) {
                int aidx = (ks*8 + wm*4 + i)*32 + lane;
                uint4 ah = sAh[aidx];
                uint4 al = sAl[aidx];
                #pragma unroll
                for (int j = 0; j < 4; j++) {
                    mma_bf16(acc[i][j], ah, bh[j]);
                    mma_bf16(acc[i][j], ah, bl[j]);
                    mma_bf16(acc[i][j], al, bh[j]);
                }
            }
        }
    }

    const int g = lane >> 2, t2 = (lane & 3) * 2;
    #pragma unroll
    for (int i = 0; i < 4; i++) {
        int r1 = m0 + wm*64 + i*16 + g;
        #pragma unroll
        for (int j = 0; j < 4; j++) {
            int cg = n0 + wn*32 + j*8 + t2;
            float2 bs = *(const float2*)(bias + cg);
            #pragma unroll
            for (int rr = 0; rr < 2; rr++) {
                int r = r1 + rr*8;
                float ex = (rr ? acc[i][j].z : acc[i][j].x) + bs.x;
                float ey = (rr ? acc[i][j].w : acc[i][j].y) + bs.y;
                if (MODE == 1) {
                    *(float2*)&Cout[(size_t)r * Ndim + cg] = make_float2(ex, ey);
                } else {
                    int b = r >> 11, s = r & 2047;
                    int part = cg >> 10, e = cg & 1023;
                    int h = e >> 6, d = e & 63, bh = b*Hh + h;
                    if (part == 0) {
                        ex *= 0.0625f; ey *= 0.0625f;   // 1/(sqrt(64)*layer_idx)
                        int mt = s >> 4, ks = d >> 4;
                        int li = (s & 7)*4 + ((d & 7) >> 1);
                        int rg = ((d >> 3) & 1)*2 + ((s >> 3) & 1);
                        int qi = (((bh*128 + mt)*4 + ks)*32 + li)*4 + rg;
                        QH[qi] = bfpack(ex, ey);
                        QL[qi] = bfpack(bflow(ex), bflow(ey));
                    } else if (part == 1) {
                        int kt = s >> 6, nt = (s & 63) >> 3;
                        int ks = d >> 4, k8 = (d >> 3) & 1;
                        int li = (s & 7)*4 + ((d & 7) >> 1);
                        int ki = ((((bh*32 + kt)*8 + nt)*4 + ks)*32 + li)*2 + k8;
                        KH[ki] = bfpack(ex, ey);
                        KL[ki] = bfpack(bflow(ex), bflow(ey));
                    } else {
                        int kt = s >> 6, kk = s & 63;
                        int ks = kk >> 4, k8 = (kk >> 3) & 1, hf = kk & 1;
                        #pragma unroll
                        for (int dd = 0; dd < 2; dd++) {
                            float v = dd ? ey : ex;
                            int d2 = d + dd;
                            int nt = d2 >> 3;
                            int li = (d2 & 7)*4 + ((kk & 7) >> 1);
                            int ui = (((((bh*32 + kt)*8 + nt)*4 + ks)*32 + li)*2 + k8)*2 + hf;
                            VHs[ui] = bfbits(v);
                            VLs[ui] = bfbits(bflow(v));
                        }
                    }
                }
            }
        }
    }
}

// ---------------------------------------------------------------------------
// Tensor-core flash attention. CTA = 128 q-rows (8 warps x 16), K-tiles of 64.
// S via bf16-split mma (Q prescaled by 1/16), fp32 online softmax in C-frags
// (quad shuffles only), P->A-frag conversion is register-local, PV via
// bf16-split mma. Epilogue writes proj-GEMM A-pack directly.
// ---------------------------------------------------------------------------
__global__ void __launch_bounds__(256)
flash_mma(const u32* __restrict__ QH, const u32* __restrict__ QL,
          const uint2* __restrict__ KH, const uint2* __restrict__ KL,
          const uint2* __restrict__ VH, const uint2* __restrict__ VL,
          u32* __restrict__ PAH, u32* __restrict__ PAL)
{
    __shared__ uint2 sKh[1024], sKl[1024], sVh[1024], sVl[1024];  // 8KB each

    const int tid = threadIdx.x, lane = tid & 31, w = tid >> 5;
    const int qt = (int)gridDim.x - 1 - (int)blockIdx.x;  // big tiles first
    const int bh = blockIdx.y;
    const int q0 = qt * 128;
    const int g = lane >> 2, t = lane & 3;

    // Q fragments for this warp's 16 rows (kept in registers whole kernel)
    uint4 Qh[4], Ql[4];
    const int mt = (q0 >> 4) + w;
    #pragma unroll
    for (int ks = 0; ks < 4; ks++) {
        int fi = ((bh*128 + mt)*4 + ks)*32 + lane;
        Qh[ks] = ((const uint4*)QH)[fi];
        Ql[ks] = ((const uint4*)QL)[fi];
    }

    float4 O[8];
    #pragma unroll
    for (int j = 0; j < 8; j++) O[j] = make_float4(0.f, 0.f, 0.f, 0.f);
    float m0_ = -1e30f, m1_ = -1e30f, l0 = 0.f, l1 = 0.f;
    const int rlo = q0 + w*16 + g, rhi = rlo + 8;
    const int wlast = q0 + w*16 + 15;   // warp's last row
    const int wfirst = q0 + w*16;       // warp's first row

    const int ntiles = 2*qt + 2;
    for (int kt = 0; kt < ntiles; kt++) {
        const uint2* srcKh = KH + (size_t)(bh*32 + kt) * 1024;
        const uint2* srcKl = KL + (size_t)(bh*32 + kt) * 1024;
        const uint2* srcVh = VH + (size_t)(bh*32 + kt) * 1024;
        const uint2* srcVl = VL + (size_t)(bh*32 + kt) * 1024;
        #pragma unroll
        for (int i = 0; i < 4; i++) {
            int idx = tid + i*256;
            sKh[idx] = srcKh[idx];
            sKl[idx] = srcKl[idx];
            sVh[idx] = srcVh[idx];
            sVl[idx] = srcVl[idx];
        }
        __syncthreads();

        const int k0 = kt * 64;
        if (k0 <= wlast) {
            // ---- S = Q K^T (scaled; 3-term split) ----
            float4 S[8];
            #pragma unroll
            for (int j = 0; j < 8; j++) S[j] = make_float4(0.f, 0.f, 0.f, 0.f);
            #pragma unroll
            for (int ks = 0; ks < 4; ks++) {
                #pragma unroll
                for (int j = 0; j < 8; j++) {
                    uint2 kb = sKh[(j*4 + ks)*32 + lane];
                    uint2 kl = sKl[(j*4 + ks)*32 + lane];
                    mma_bf16(S[j], Qh[ks], kb);
                    mma_bf16(S[j], Qh[ks], kl);
                    mma_bf16(S[j], Ql[ks], kb);
                }
            }
            // ---- causal mask (ref: masked = -10000 after scaling) ----
            if (k0 + 63 > wfirst) {
                #pragma unroll
                for (int j = 0; j < 8; j++) {
                    int c0 = k0 + j*8 + 2*t, c1 = c0 + 1;
                    if (c0 > rlo) S[j].x = -10000.f;
                    if (c1 > rlo) S[j].y = -10000.f;
                    if (c0 > rhi) S[j].z = -10000.f;
                    if (c1 > rhi) S[j].w = -10000.f;
                }
            }
            // ---- online softmax (rows g / g+8; reduce over quad) ----
            float mx0 = -1e30f, mx1 = -1e30f;
            #pragma unroll
            for (int j = 0; j < 8; j++) {
                mx0 = fmaxf(mx0, fmaxf(S[j].x, S[j].y));
                mx1 = fmaxf(mx1, fmaxf(S[j].z, S[j].w));
            }
            mx0 = fmaxf(mx0, __shfl_xor_sync(0xffffffffu, mx0, 1));
            mx0 = fmaxf(mx0, __shfl_xor_sync(0xffffffffu, mx0, 2));
            mx1 = fmaxf(mx1, __shfl_xor_sync(0xffffffffu, mx1, 1));
            mx1 = fmaxf(mx1, __shfl_xor_sync(0xffffffffu, mx1, 2));
            float mn0 = fmaxf(m0_, mx0), mn1 = fmaxf(m1_, mx1);
            float c0 = __expf(m0_ - mn0), c1 = __expf(m1_ - mn1);
            m0_ = mn0; m1_ = mn1;
            float s0 = 0.f, s1 = 0.f;
            #pragma unroll
            for (int j = 0; j < 8; j++) {
                S[j].x = __expf(S[j].x - mn0);
                S[j].y = __expf(S[j].y - mn0);
                S[j].z = __expf(S[j].z - mn1);
                S[j].w = __expf(S[j].w - mn1);
                s0 += S[j].x + S[j].y;
                s1 += S[j].z + S[j].w;
            }
            s0 += __shfl_xor_sync(0xffffffffu, s0, 1);
            s0 += __shfl_xor_sync(0xffffffffu, s0, 2);
            s1 += __shfl_xor_sync(0xffffffffu, s1, 1);
            s1 += __shfl_xor_sync(0xffffffffu, s1, 2);
            l0 = l0*c0 + s0;
            l1 = l1*c1 + s1;
            #pragma unroll
            for (int j = 0; j < 8; j++) {
                O[j].x *= c0; O[j].y *= c0;
                O[j].z *= c1; O[j].w *= c1;
            }
            // ---- P (C-frag) -> A-frag, register-local; O += P V ----
            #pragma unroll
            for (int kc = 0; kc < 4; kc++) {
                float4 A = S[2*kc], B = S[2*kc + 1];
                uint4 ph, pl;
                ph.x = bfpack(A.x, A.y); ph.y = bfpack(A.z, A.w);
                ph.z = bfpack(B.x, B.y); ph.w = bfpack(B.z, B.w);
                pl.x = bfpack(bflow(A.x), bflow(A.y));
                pl.y = bfpack(bflow(A.z), bflow(A.w));
                pl.z = bfpack(bflow(B.x), bflow(B.y));
                pl.w = bfpack(bflow(B.z), bflow(B.w));
                #pragma unroll
                for (int j = 0; j < 8; j++) {
                    uint2 vh = sVh[(j*4 + kc)*32 + lane];
                    uint2 vl = sVl[(j*4 + kc)*32 + lane];
                    mma_bf16(O[j], ph, vh);
                    mma_bf16(O[j], ph, vl);
                    mma_bf16(O[j], pl, vh);
                }
            }
        }
        __syncthreads();
    }

    // ---- epilogue: normalize + write proj A-pack (hi/lo) ----
    const float i0 = 1.f / l0, i1 = 1.f / l1;
    const int b = bh >> 4, h = bh & 15;
    const int mtp = (b*2048 + q0 + w*16) >> 4;   // row bit3: 0 for g, 1 for g+8
    #pragma unroll
    for (int j = 0; j < 8; j++) {
        int e = h*64 + j*8;                      // + 2t handled via lane slot
        int ksp = (e >> 4) | 0;                  // = h*4 + (j>>1)
        ksp = h*4 + (j >> 1);
        int base = ((mtp*64 + ksp)*32 + g*4 + t)*4 + (j & 1)*2;
        float x = O[j].x * i0, y = O[j].y * i0;
        float z = O[j].z * i1, wv = O[j].w * i1;
        PAH[base + 0] = bfpack(x, y);
        PAL[base + 0] = bfpack(bflow(x), bflow(y));
        PAH[base + 1] = bfpack(z, wv);
        PAL[base + 1] = bfpack(bflow(z), bflow(wv));
    }
}

// ---------------------------------------------------------------------------
extern "C" void kernel_launch(void* const* d_in, const int* in_sizes, int n_in,
                              void* d_out, int out_size)
{
    const float* hs     = (const float*)d_in[0];
    const float* w_attn = (const float*)d_in[1];
    const float* b_attn = (const float*)d_in[2];
    const float* w_proj = (const float*)d_in[3];
    const float* b_proj = (const float*)d_in[4];
    float* out = (float*)d_out;

    uint4 *pxh, *pxl, *pah, *pal, *pwah, *pwal, *pwph, *pwpl;
    u32 *qph, *qpl, *kph, *kpl, *vph, *vpl;
    cudaGetSymbolAddress((void**)&pxh,  g_pxh);  cudaGetSymbolAddress((void**)&pxl,  g_pxl);
    cudaGetSymbolAddress((void**)&pah,  g_pah);  cudaGetSymbolAddress((void**)&pal,  g_pal);
    cudaGetSymbolAddress((void**)&pwah, g_pwah); cudaGetSymbolAddress((void**)&pwal, g_pwal);
    cudaGetSymbolAddress((void**)&pwph, g_pwph); cudaGetSymbolAddress((void**)&pwpl, g_pwpl);
    cudaGetSymbolAddress((void**)&qph,  g_qph);  cudaGetSymbolAddress((void**)&qpl,  g_qpl);
    cudaGetSymbolAddress((void**)&kph,  g_kph);  cudaGetSymbolAddress((void**)&kpl,  g_kpl);
    cudaGetSymbolAddress((void**)&vph,  g_vph);  cudaGetSymbolAddress((void**)&vpl,  g_vpl);

    // 0) pack inputs (split + fragment layout)
    split_pack_A<<<(Bb*Ss*Ee)/(256*8), 256>>>(hs, pxh, pxl);
    tsplit_pack_B<<<dim3(3*Ee/32, Ee/32), 256>>>(w_attn, pwah, pwal, 3*Ee);
    tsplit_pack_B<<<dim3(Ee/32,   Ee/32), 256>>>(w_proj, pwph, pwpl, Ee);

    // 1) QKV GEMM (tensor cores); epilogue packs Q(1/16)/K/V flash fragments
    gemm_mma<0><<<dim3(3*Ee/128, (Bb*Ss)/128), 256>>>(
        pxh, pxl, pwah, pwal, b_attn, nullptr,
        qph, qpl, kph, kpl, (u16*)vph, (u16*)vpl, 3*Ee);

    // 2) causal flash attention (tensor cores); writes proj A-pack
    flash_mma<<<dim3(Ss/128, BHh), 256>>>(
        qph, qpl, (const uint2*)kph, (const uint2*)kpl,
        (const uint2*)vph, (const uint2*)vpl, (u32*)pah, (u32*)pal);

    // 3) projection GEMM (tensor cores) -> d_out
    gemm_mma<1><<<dim3(Ee/128, (Bb*Ss)/128), 256>>>(
        pah, pal, pwph, pwpl, b_proj, out,
        nullptr, nullptr, nullptr, nullptr, nullptr, nullptr, Ee);
}

// round 16
// speedup vs baseline: 3.5067x; 1.1857x over previous
#include <cuda_runtime.h>
#include <cuda_bf16.h>
#include <cstdint>

// Problem constants
#define Bb 2
#define Ss 2048
#define Ee 1024
#define Hh 16
#define Dd 64
#define BHh (Bb*Hh)

typedef unsigned int u32;
typedef unsigned short u16;

// ---------------- device scratch (no allocations allowed) ----------------
__device__ uint4 g_pxh[256*64*32], g_pxl[256*64*32];   // hidden A-pack
__device__ uint4 g_pah[256*64*32], g_pal[256*64*32];   // attn-out A-pack (proj input)
__device__ uint4 g_pwah[384*64*16], g_pwal[384*64*16]; // W_attn^T B-pack
__device__ uint4 g_pwph[128*64*16], g_pwpl[128*64*16]; // W_proj^T B-pack
// Flash packs (per bh): Q A-pack (m=s,k=d), K B-pack (n=key,k=d), V B-pack (n=d,k=key)
__device__ u32 g_qph[32*128*4*32*4], g_qpl[32*128*4*32*4];
__device__ u32 g_kph[32*32*8*4*32*2], g_kpl[32*32*8*4*32*2];
__device__ u32 g_vph[32*32*8*4*32*2], g_vpl[32*32*8*4*32*2];

__device__ __forceinline__ u32 bfpack(float a, float b) {
    __nv_bfloat16 ha = __float2bfloat16(a), hb = __float2bfloat16(b);
    return (u32)__bfloat16_as_ushort(ha) | ((u32)__bfloat16_as_ushort(hb) << 16);
}
__device__ __forceinline__ float bflow(float x) {
    return x - __bfloat162float(__float2bfloat16(x));
}
__device__ __forceinline__ u16 bfbits(float x) {
    return __bfloat16_as_ushort(__float2bfloat16(x));
}
__device__ __forceinline__ u32 smem_u32(const void* p) {
    u32 a; asm("{ .reg .u64 t; cvta.to.shared.u64 t, %1; cvt.u32.u64 %0, t; }" : "=r"(a) : "l"(p));
    return a;
}
// cp.async helpers (sm_80+, OK under compute_103)
__device__ __forceinline__ void cp16(u32 s, const void* g) {
    asm volatile("cp.async.cg.shared.global [%0], [%1], 16;" :: "r"(s), "l"(g));
}
__device__ __forceinline__ void cp_commit() { asm volatile("cp.async.commit_group;"); }
__device__ __forceinline__ void cp_wait1()  { asm volatile("cp.async.wait_group 1;"); }
__device__ __forceinline__ void cp_wait0()  { asm volatile("cp.async.wait_group 0;"); }

// ---------------- mma.sync wrapper (bf16 -> fp32) ----------------
__device__ __forceinline__ void mma_bf16(float4& c, uint4 a, uint2 b) {
    asm volatile("mma.sync.aligned.m16n8k16.row.col.f32.bf16.bf16.f32 "
        "{%0,%1,%2,%3}, {%4,%5,%6,%7}, {%8,%9}, {%0,%1,%2,%3};"
        : "+f"(c.x), "+f"(c.y), "+f"(c.z), "+f"(c.w)
        : "r"(a.x), "r"(a.y), "r"(a.z), "r"(a.w), "r"(b.x), "r"(b.y));
}

// ---------------- pre-pass: split fp32 activations -> packed bf16 hi/lo ----
__global__ void __launch_bounds__(256)
split_pack_A(const float* __restrict__ X, uint4* __restrict__ H4, uint4* __restrict__ L4)
{
    u32* H = (u32*)H4; u32* L = (u32*)L4;
    int gid = blockIdx.x * 256 + threadIdx.x;   // one per 8 elems
    int m = gid >> 7;
    int kg = (gid & 127) * 8;
    const float* p = X + (size_t)m * 1024 + kg;
    float4 v0 = *(const float4*)p, v1 = *(const float4*)(p + 4);
    float xs[8] = {v0.x, v0.y, v0.z, v0.w, v1.x, v1.y, v1.z, v1.w};
    int mt = m >> 4, ks = kg >> 4, mhi = (m >> 3) & 1, k8 = (kg >> 3) & 1;
    int base = (((mt*64 + ks)*32) + (m & 7)*4) * 4 + (k8*2 + mhi);
    #pragma unroll
    for (int t = 0; t < 4; t++) {
        float e0 = xs[2*t], e1 = xs[2*t+1];
        H[base + t*4] = bfpack(e0, e1);
        L[base + t*4] = bfpack(bflow(e0), bflow(e1));
    }
}

// ---------------- pre-pass: transpose+split weights -> packed bf16 hi/lo ---
__global__ void __launch_bounds__(256)
tsplit_pack_B(const float* __restrict__ W, uint4* __restrict__ H4, uint4* __restrict__ L4, int N)
{
    u32* H = (u32*)H4; u32* L = (u32*)L4;
    __shared__ float t[32][33];
    const int k0 = blockIdx.y * 32, n0 = blockIdx.x * 32;
    const int r = threadIdx.x >> 3, c4 = (threadIdx.x & 7) * 4;
    float4 v = *(const float4*)&W[(size_t)(k0 + r) * N + n0 + c4];
    t[r][c4+0] = v.x; t[r][c4+1] = v.y; t[r][c4+2] = v.z; t[r][c4+3] = v.w;
    __syncthreads();
    const int n = n0 + r, kk = k0 + c4;
    float e[4];
    #pragma unroll
    for (int i = 0; i < 4; i++) e[i] = t[c4 + i][r];
    int nt = n >> 3, ks = kk >> 4, k8 = (kk >> 3) & 1;
    int tp = (kk & 7) >> 1;
    int idx = (((nt*64 + ks)*32) + (n & 7)*4 + tp) * 2 + k8;
    H[idx]     = bfpack(e[0], e[1]);
    H[idx + 2] = bfpack(e[2], e[3]);
    L[idx]     = bfpack(bflow(e[0]), bflow(e[1]));
    L[idx + 2] = bfpack(bflow(e[2]), bflow(e[3]));
}

// ---------------- tensor-core (mma.sync) bf16-split GEMM ----------------
// cp.async 2-stage pipeline, 2 CTAs/SM. Dyn smem: stage s (32KB) at uint4
// offset s*2048: Ah[0,512) Al[512,1024) Bh[1024,1536) Bl[1536,2048).
template<int MODE>
__global__ void __launch_bounds__(256, 2)
gemm_mma(const uint4* __restrict__ Ah, const uint4* __restrict__ Al,
         const uint4* __restrict__ Bh, const uint4* __restrict__ Bl,
         const float* __restrict__ bias, float* __restrict__ Cout,
         u32* __restrict__ QH, u32* __restrict__ QL,
         u32* __restrict__ KH, u32* __restrict__ KL,
         u16* __restrict__ VHs, u16* __restrict__ VLs,
         int Ndim)
{
    extern __shared__ uint4 dynsm[];
    const u32 sbase = smem_u32(dynsm);

    const int tid = threadIdx.x;
    const int lane = tid & 31, wid = tid >> 5;
    const int wm = wid & 1, wn = wid >> 1;
    const int m0 = blockIdx.y * 128, n0 = blockIdx.x * 128;
    const int m0t = m0 >> 4, n0t = n0 >> 3;

    const int ia0 = tid, ia1 = tid + 256;
    #define A_G(idx) ((((size_t)(m0t + ((idx) >> 6)) * 64 + (((idx) >> 5) & 1)) * 32) + ((idx) & 31))
    #define A_S(idx) (((((idx) >> 5) & 1) * 8 + ((idx) >> 6)) * 32 + ((idx) & 31))
    #define B_G(idx) ((((size_t)(n0t + ((idx) >> 5)) * 64 + (((idx) >> 4) & 1)) * 16) + ((idx) & 15))
    #define B_S(idx) (((((idx) >> 4) & 1) * 16 + ((idx) >> 5)) * 16 + ((idx) & 15))
    const uint4 *pAh0 = Ah + A_G(ia0), *pAh1 = Ah + A_G(ia1);
    const uint4 *pAl0 = Al + A_G(ia0), *pAl1 = Al + A_G(ia1);
    const uint4 *pBh0 = Bh + B_G(ia0), *pBh1 = Bh + B_G(ia1);
    const uint4 *pBl0 = Bl + B_G(ia0), *pBl1 = Bl + B_G(ia1);
    const u32 sa0 = (u32)A_S(ia0)*16, sa1 = (u32)A_S(ia1)*16;
    const u32 sb0 = (u32)B_S(ia0)*16, sb1 = (u32)B_S(ia1)*16;

    #define ISSUE(CK) do { \
        u32 bb = sbase + ((CK) & 1) * 32768; \
        size_t ao = (size_t)(CK)*64, bo = (size_t)(CK)*32; \
        cp16(bb + sa0, pAh0 + ao);          cp16(bb + sa1, pAh1 + ao); \
        cp16(bb + 8192 + sa0, pAl0 + ao);   cp16(bb + 8192 + sa1, pAl1 + ao); \
        cp16(bb + 16384 + sb0, pBh0 + bo);  cp16(bb + 16384 + sb1, pBh1 + bo); \
        cp16(bb + 24576 + sb0, pBl0 + bo);  cp16(bb + 24576 + sb1, pBl1 + bo); \
        cp_commit(); \
    } while (0)

    float4 acc[4][4];
    #pragma unroll
    for (int i = 0; i < 4; i++)
        #pragma unroll
        for (int j = 0; j < 4; j++) acc[i][j] = make_float4(0.f, 0.f, 0.f, 0.f);

    ISSUE(0);
    for (int ck = 0; ck < 32; ck++) {
        if (ck + 1 < 32) { ISSUE(ck + 1); cp_wait1(); }
        else             { cp_wait0(); }
        __syncthreads();

        const uint4* st4  = dynsm + (ck & 1) * 2048;
        const uint4* stAh = st4;
        const uint4* stAl = st4 + 512;
        const uint2* stBh = (const uint2*)(st4 + 1024);
        const uint2* stBl = (const uint2*)(st4 + 1536);

        #pragma unroll
        for (int ks = 0; ks < 2; ks++) {
            uint2 bh[4], bl[4];
            #pragma unroll
            for (int j = 0; j < 4; j++) {
                int bi = (ks*16 + wn*4 + j)*32 + lane;
                bh[j] = stBh[bi];
                bl[j] = stBl[bi];
            }
            #pragma unroll
            for (int i = 0; i < 4; i++) {
                int aidx = (ks*8 + wm*4 + i)*32 + lane;
                uint4 ah = stAh[aidx];
                uint4 al = stAl[aidx];
                #pragma unroll
                for (int j = 0; j < 4; j++) {
                    mma_bf16(acc[i][j], ah, bh[j]);
                    mma_bf16(acc[i][j], ah, bl[j]);
                    mma_bf16(acc[i][j], al, bh[j]);
                }
            }
        }
        __syncthreads();
    }

    const int g = lane >> 2, t2 = (lane & 3) * 2;
    #pragma unroll
    for (int i = 0; i < 4; i++) {
        int r1 = m0 + wm*64 + i*16 + g;
        #pragma unroll
        for (int j = 0; j < 4; j++) {
            int cg = n0 + wn*32 + j*8 + t2;
            float2 bs = *(const float2*)(bias + cg);
            #pragma unroll
            for (int rr = 0; rr < 2; rr++) {
                int r = r1 + rr*8;
                float ex = (rr ? acc[i][j].z : acc[i][j].x) + bs.x;
                float ey = (rr ? acc[i][j].w : acc[i][j].y) + bs.y;
                if (MODE == 1) {
                    *(float2*)&Cout[(size_t)r * Ndim + cg] = make_float2(ex, ey);
                } else {
                    int b = r >> 11, s = r & 2047;
                    int part = cg >> 10, e = cg & 1023;
                    int h = e >> 6, d = e & 63, bh = b*Hh + h;
                    if (part == 0) {
                        ex *= 0.0625f; ey *= 0.0625f;   // 1/(sqrt(64)*layer_idx)
                        int mt = s >> 4, ks = d >> 4;
                        int li = (s & 7)*4 + ((d & 7) >> 1);
                        int rg = ((d >> 3) & 1)*2 + ((s >> 3) & 1);
                        int qi = (((bh*128 + mt)*4 + ks)*32 + li)*4 + rg;
                        QH[qi] = bfpack(ex, ey);
                        QL[qi] = bfpack(bflow(ex), bflow(ey));
                    } else if (part == 1) {
                        int kt = s >> 6, nt = (s & 63) >> 3;
                        int ks = d >> 4, k8 = (d >> 3) & 1;
                        int li = (s & 7)*4 + ((d & 7) >> 1);
                        int ki = ((((bh*32 + kt)*8 + nt)*4 + ks)*32 + li)*2 + k8;
                        KH[ki] = bfpack(ex, ey);
                        KL[ki] = bfpack(bflow(ex), bflow(ey));
                    } else {
                        int kt = s >> 6, kk = s & 63;
                        int ks = kk >> 4, k8 = (kk >> 3) & 1, hf = kk & 1;
                        #pragma unroll
                        for (int dd = 0; dd < 2; dd++) {
                            float v = dd ? ey : ex;
                            int d2 = d + dd;
                            int nt = d2 >> 3;
                            int li = (d2 & 7)*4 + ((kk & 7) >> 1);
                            int ui = (((((bh*32 + kt)*8 + nt)*4 + ks)*32 + li)*2 + k8)*2 + hf;
                            VHs[ui] = bfbits(v);
                            VLs[ui] = bfbits(bflow(v));
                        }
                    }
                }
            }
        }
    }
}

// ---------------------------------------------------------------------------
// Tensor-core flash attention, cp.async 2-stage K/V pipeline.
// Dyn smem: stage s (32KB) at uint4 offset s*2048:
//   Kh[0,512) Kl[512,1024) Vh[1024,1536) Vl[1536,2048).
// ---------------------------------------------------------------------------
__global__ void __launch_bounds__(256)
flash_mma(const u32* __restrict__ QH, const u32* __restrict__ QL,
          const uint2* __restrict__ KH, const uint2* __restrict__ KL,
          const uint2* __restrict__ VH, const uint2* __restrict__ VL,
          u32* __restrict__ PAH, u32* __restrict__ PAL)
{
    extern __shared__ uint4 dynsm[];
    const u32 sbase = smem_u32(dynsm);

    const int tid = threadIdx.x, lane = tid & 31, w = tid >> 5;
    const int qt = (int)gridDim.x - 1 - (int)blockIdx.x;  // big tiles first
    const int bh = blockIdx.y;
    const int q0 = qt * 128;
    const int g = lane >> 2, t = lane & 3;

    // Q fragments for this warp's 16 rows (registers, whole kernel)
    uint4 Qh[4], Ql[4];
    const int mt = (q0 >> 4) + w;
    #pragma unroll
    for (int ks = 0; ks < 4; ks++) {
        int fi = ((bh*128 + mt)*4 + ks)*32 + lane;
        Qh[ks] = ((const uint4*)QH)[fi];
        Ql[ks] = ((const uint4*)QL)[fi];
    }

    float4 O[8];
    #pragma unroll
    for (int j = 0; j < 8; j++) O[j] = make_float4(0.f, 0.f, 0.f, 0.f);
    float m0_ = -1e30f, m1_ = -1e30f, l0 = 0.f, l1 = 0.f;
    const int rlo = q0 + w*16 + g, rhi = rlo + 8;
    const int wlast = q0 + w*16 + 15;
    const int wfirst = q0 + w*16;

    const int ntiles = 2*qt + 2;

    #define FISSUE(KT) do { \
        u32 bb = sbase + ((KT) & 1) * 32768; \
        size_t toff = (size_t)(bh*32 + (KT)) * 512; \
        const uint4* gkh = (const uint4*)KH + toff; \
        const uint4* gkl = (const uint4*)KL + toff; \
        const uint4* gvh = (const uint4*)VH + toff; \
        const uint4* gvl = (const uint4*)VL + toff; \
        cp16(bb + tid*16, gkh + tid);                 cp16(bb + (tid+256)*16, gkh + tid + 256); \
        cp16(bb + 8192 + tid*16, gkl + tid);          cp16(bb + 8192 + (tid+256)*16, gkl + tid + 256); \
        cp16(bb + 16384 + tid*16, gvh + tid);         cp16(bb + 16384 + (tid+256)*16, gvh + tid + 256); \
        cp16(bb + 24576 + tid*16, gvl + tid);         cp16(bb + 24576 + (tid+256)*16, gvl + tid + 256); \
        cp_commit(); \
    } while (0)

    FISSUE(0);
    for (int kt = 0; kt < ntiles; kt++) {
        if (kt + 1 < ntiles) { FISSUE(kt + 1); cp_wait1(); }
        else                 { cp_wait0(); }
        __syncthreads();

        const uint4* st4 = dynsm + (kt & 1) * 2048;
        const uint2* sKh = (const uint2*)st4;
        const uint2* sKl = (const uint2*)(st4 + 512);
        const uint2* sVh = (const uint2*)(st4 + 1024);
        const uint2* sVl = (const uint2*)(st4 + 1536);

        const int k0 = kt * 64;
        if (k0 <= wlast) {
            // ---- S = Q K^T (scaled; 3-term split) ----
            float4 S[8];
            #pragma unroll
            for (int j = 0; j < 8; j++) S[j] = make_float4(0.f, 0.f, 0.f, 0.f);
            #pragma unroll
            for (int ks = 0; ks < 4; ks++) {
                #pragma unroll
                for (int j = 0; j < 8; j++) {
                    uint2 kb = sKh[(j*4 + ks)*32 + lane];
                    uint2 kl = sKl[(j*4 + ks)*32 + lane];
                    mma_bf16(S[j], Qh[ks], kb);
                    mma_bf16(S[j], Qh[ks], kl);
                    mma_bf16(S[j], Ql[ks], kb);
                }
            }
            // ---- causal mask ----
            if (k0 + 63 > wfirst) {
                #pragma unroll
                for (int j = 0; j < 8; j++) {
                    int c0 = k0 + j*8 + 2*t, c1 = c0 + 1;
                    if (c0 > rlo) S[j].x = -10000.f;
                    if (c1 > rlo) S[j].y = -10000.f;
                    if (c0 > rhi) S[j].z = -10000.f;
                    if (c1 > rhi) S[j].w = -10000.f;
                }
            }
            // ---- online softmax (rows g / g+8; quad reduce) ----
            float mx0 = -1e30f, mx1 = -1e30f;
            #pragma unroll
            for (int j = 0; j < 8; j++) {
                mx0 = fmaxf(mx0, fmaxf(S[j].x, S[j].y));
                mx1 = fmaxf(mx1, fmaxf(S[j].z, S[j].w));
            }
            mx0 = fmaxf(mx0, __shfl_xor_sync(0xffffffffu, mx0, 1));
            mx0 = fmaxf(mx0, __shfl_xor_sync(0xffffffffu, mx0, 2));
            mx1 = fmaxf(mx1, __shfl_xor_sync(0xffffffffu, mx1, 1));
            mx1 = fmaxf(mx1, __shfl_xor_sync(0xffffffffu, mx1, 2));
            float mn0 = fmaxf(m0_, mx0), mn1 = fmaxf(m1_, mx1);
            float c0 = __expf(m0_ - mn0), c1 = __expf(m1_ - mn1);
            m0_ = mn0; m1_ = mn1;
            float s0 = 0.f, s1 = 0.f;
            #pragma unroll
            for (int j = 0; j < 8; j++) {
                S[j].x = __expf(S[j].x - mn0);
                S[j].y = __expf(S[j].y - mn0);
                S[j].z = __expf(S[j].z - mn1);
                S[j].w = __expf(S[j].w - mn1);
                s0 += S[j].x + S[j].y;
                s1 += S[j].z + S[j].w;
            }
            s0 += __shfl_xor_sync(0xffffffffu, s0, 1);
            s0 += __shfl_xor_sync(0xffffffffu, s0, 2);
            s1 += __shfl_xor_sync(0xffffffffu, s1, 1);
            s1 += __shfl_xor_sync(0xffffffffu, s1, 2);
            l0 = l0*c0 + s0;
            l1 = l1*c1 + s1;
            #pragma unroll
            for (int j = 0; j < 8; j++) {
                O[j].x *= c0; O[j].y *= c0;
                O[j].z *= c1; O[j].w *= c1;
            }
            // ---- P (C-frag) -> A-frag register-local; O += P V ----
            #pragma unroll
            for (int kc = 0; kc < 4; kc++) {
                float4 A = S[2*kc], B = S[2*kc + 1];
                uint4 ph, pl;
                ph.x = bfpack(A.x, A.y); ph.y = bfpack(A.z, A.w);
                ph.z = bfpack(B.x, B.y); ph.w = bfpack(B.z, B.w);
                pl.x = bfpack(bflow(A.x), bflow(A.y));
                pl.y = bfpack(bflow(A.z), bflow(A.w));
                pl.z = bfpack(bflow(B.x), bflow(B.y));
                pl.w = bfpack(bflow(B.z), bflow(B.w));
                #pragma unroll
                for (int j = 0; j < 8; j++) {
                    uint2 vh = sVh[(j*4 + kc)*32 + lane];
                    uint2 vl = sVl[(j*4 + kc)*32 + lane];
                    mma_bf16(O[j], ph, vh);
                    mma_bf16(O[j], ph, vl);
                    mma_bf16(O[j], pl, vh);
                }
            }
        }
        __syncthreads();
    }

    // ---- epilogue: normalize + write proj A-pack (hi/lo) ----
    const float i0 = 1.f / l0, i1 = 1.f / l1;
    const int b = bh >> 4, h = bh & 15;
    const int mtp = (b*2048 + q0 + w*16) >> 4;
    #pragma unroll
    for (int j = 0; j < 8; j++) {
        int ksp = h*4 + (j >> 1);
        int base = ((mtp*64 + ksp)*32 + g*4 + t)*4 + (j & 1)*2;
        float x = O[j].x * i0, y = O[j].y * i0;
        float z = O[j].z * i1, wv = O[j].w * i1;
        PAH[base + 0] = bfpack(x, y);
        PAL[base + 0] = bfpack(bflow(x), bflow(y));
        PAH[base + 1] = bfpack(z, wv);
        PAL[base + 1] = bfpack(bflow(z), bflow(wv));
    }
}

// ---------------------------------------------------------------------------
extern "C" void kernel_launch(void* const* d_in, const int* in_sizes, int n_in,
                              void* d_out, int out_size)
{
    const float* hs     = (const float*)d_in[0];
    const float* w_attn = (const float*)d_in[1];
    const float* b_attn = (const float*)d_in[2];
    const float* w_proj = (const float*)d_in[3];
    const float* b_proj = (const float*)d_in[4];
    float* out = (float*)d_out;

    uint4 *pxh, *pxl, *pah, *pal, *pwah, *pwal, *pwph, *pwpl;
    u32 *qph, *qpl, *kph, *kpl, *vph, *vpl;
    cudaGetSymbolAddress((void**)&pxh,  g_pxh);  cudaGetSymbolAddress((void**)&pxl,  g_pxl);
    cudaGetSymbolAddress((void**)&pah,  g_pah);  cudaGetSymbolAddress((void**)&pal,  g_pal);
    cudaGetSymbolAddress((void**)&pwah, g_pwah); cudaGetSymbolAddress((void**)&pwal, g_pwal);
    cudaGetSymbolAddress((void**)&pwph, g_pwph); cudaGetSymbolAddress((void**)&pwpl, g_pwpl);
    cudaGetSymbolAddress((void**)&qph,  g_qph);  cudaGetSymbolAddress((void**)&qpl,  g_qpl);
    cudaGetSymbolAddress((void**)&kph,  g_kph);  cudaGetSymbolAddress((void**)&kpl,  g_kpl);
    cudaGetSymbolAddress((void**)&vph,  g_vph);  cudaGetSymbolAddress((void**)&vpl,  g_vpl);

    const int gemm_smem  = 65536;   // 2 stages x 32KB
    const int flash_smem = 65536;
    cudaFuncSetAttribute(gemm_mma<0>, cudaFuncAttributeMaxDynamicSharedMemorySize, gemm_smem);
    cudaFuncSetAttribute(gemm_mma<1>, cudaFuncAttributeMaxDynamicSharedMemorySize, gemm_smem);
    cudaFuncSetAttribute(flash_mma,   cudaFuncAttributeMaxDynamicSharedMemorySize, flash_smem);

    // 0) pack inputs (split + fragment layout)
    split_pack_A<<<(Bb*Ss*Ee)/(256*8), 256>>>(hs, pxh, pxl);
    tsplit_pack_B<<<dim3(3*Ee/32, Ee/32), 256>>>(w_attn, pwah, pwal, 3*Ee);
    tsplit_pack_B<<<dim3(Ee/32,   Ee/32), 256>>>(w_proj, pwph, pwpl, Ee);

    // 1) QKV GEMM (tensor cores); epilogue packs Q(1/16)/K/V flash fragments
    gemm_mma<0><<<dim3(3*Ee/128, (Bb*Ss)/128), 256, gemm_smem>>>(
        pxh, pxl, pwah, pwal, b_attn, nullptr,
        qph, qpl, kph, kpl, (u16*)vph, (u16*)vpl, 3*Ee);

    // 2) causal flash attention (tensor cores); writes proj A-pack
    flash_mma<<<dim3(Ss/128, BHh), 256, flash_smem>>>(
        qph, qpl, (const uint2*)kph, (const uint2*)kpl,
        (const uint2*)vph, (const uint2*)vpl, (u32*)pah, (u32*)pal);

    // 3) projection GEMM (tensor cores) -> d_out
    gemm_mma<1><<<dim3(Ee/128, (Bb*Ss)/128), 256, gemm_smem>>>(
        pah, pal, pwph, pwpl, b_proj, out,
        nullptr, nullptr, nullptr, nullptr, nullptr, nullptr, Ee);
}